// round 14
// baseline (speedup 1.0000x reference)
#include <cuda_runtime.h>
#include <cstdint>

#define HH 512
#define WW 512
#define TBINS 180
#define RBINS 360
#define NPIX (HH*WW)
#define CDF_BLOCKS 2048       // 16384 warps
#define NCG 12                // column groups of 32 buckets
#define NTL 6                 // theta tiles of 30 rows
#define NSP 16                // pixel splits in vote

// scratch (no cudaMalloc allowed)
static __device__ float4 g_pts[NPIX];       // theta, rho, sig_t, sig_r (raw order)
static __device__ float  g_val[NPIX];       // mask value (raw order)
static __device__ int    g_misc[721];       // [0]=count, [1..360]=bcnt, [361..720]=bfill
static __device__ int    g_boff[361];       // bucket prefix offsets
static __device__ float  g_wt[(size_t)NPIX * 180]; // theta weights, BUCKET order
static __device__ float  g_wr[(size_t)NPIX * 32];  // rho weights (32, zero-pad), BUCKET order

// bin-edge constants
#define TMIN_F (-1.5707963267948966f)
#define TBIN_F ((float)(3.14159265358979323846 / 179.0))
#define RMAX_D 724.07734393502470
#define RMIN_F ((float)(-RMAX_D))
#define RBIN_F ((float)(2.0 * RMAX_D / 359.0))

__device__ __forceinline__ float fcdf(float x) {
    return 0.5f * (1.0f + erff(x * 0.7071067811865476f));
}

// rlo from (rho, sig_r): MUST be identical text in plane and cdf.
__device__ __forceinline__ int calc_rlo(float rho, float sig_r) {
    float Wr = fminf(6.5f * sig_r, 62.0f);
    int rklo = max(0, (int)ceilf((rho - Wr - RMIN_F) / RBIN_F + 0.5f));
    rklo = min(rklo, 360);
    return min(max(0, rklo - 1), 359);
}

// ---------------- plane: fit + validity (bit-exact) + compact + rlo histogram ----------------
__global__ void plane_kernel(const float* __restrict__ img,
                             const float* __restrict__ mask,
                             float* __restrict__ out) {
    int bid = blockIdx.y * (WW / 32) + blockIdx.x;
    int zi = bid * 256 + threadIdx.y * 32 + threadIdx.x;
    if (zi < (TBINS * RBINS) / 4)
        ((float4*)out)[zi] = make_float4(0.f, 0.f, 0.f, 0.f);

    int w = blockIdx.x * 32 + threadIdx.x;
    int h = blockIdx.y * 8  + threadIdx.y;
    int hm = max(h - 1, 0), hp = min(h + 1, HH - 1);
    int wm = max(w - 1, 0), wp = min(w + 1, WW - 1);
    const float* r0 = img + hm * WW;
    const float* r1 = img + h  * WW;
    const float* r2 = img + hp * WW;
    float a00 = r0[wm], a01 = r0[w], a02 = r0[wp];
    float a10 = r1[wm], a11 = r1[w], a12 = r1[wp];
    float a20 = r2[wm], a21 = r2[w], a22 = r2[wp];

    float asum = __fadd_rn(__fadd_rn(__fadd_rn(__fadd_rn(__fadd_rn(
                 -a00, -a01), -a02), a20), a21), a22);
    float bsum = __fadd_rn(__fadd_rn(__fadd_rn(__fadd_rn(__fadd_rn(
                 -a00, a02), -a10), a12), -a20), a22);
    float gsum = __fadd_rn(__fadd_rn(__fadd_rn(__fadd_rn(__fadd_rn(__fadd_rn(
                 __fadd_rn(__fadd_rn(a00, a01), a02), a10), a11), a12), a20), a21), a22);

    float alpha = __fadd_rn(__fdiv_rn(asum, 6.0f), 1e-6f);
    float beta  = __fadd_rn(__fdiv_rn(bsum, 6.0f), 1e-6f);
    float gamma = __fdiv_rn(gsum, 9.0f);

    float rs_arr[3] = { a01, a11, a21 };
    float bd_arr[3] = { -beta, 0.0f, beta };
    float ad_arr[3] = { -alpha, 0.0f, alpha };
    float eps2 = 0.0f;
#pragma unroll
    for (int i = 0; i < 3; i++)
#pragma unroll
        for (int j = 0; j < 3; j++) {
            float r = __fsub_rn(__fsub_rn(__fsub_rn(rs_arr[i], ad_arr[j]), bd_arr[i]), gamma);
            eps2 = __fadd_rn(eps2, __fmul_rn(r, r));
        }
    float nv = __fdiv_rn(eps2, 7.0f);
    float va = __fdiv_rn(nv, 6.0f);

    float aa = __fmul_rn(alpha, alpha);
    float bb = __fmul_rn(beta, beta);
    float g2 = __fadd_rn(aa, bb);
    float num = __fadd_rn(__fmul_rn(bb, va), __fmul_rn(aa, va));
    float var_t = __fdiv_rn(num, __fmul_rn(g2, g2));

    float theta = atanf(__fdiv_rn(beta, alpha));
    float inv = rsqrtf(g2);
    float invs = copysignf(inv, alpha);
    float ct = alpha * invs;
    float st = beta  * invs;
    float xf = (float)h, yf = (float)w;
    float rho  = __fadd_rn(__fmul_rn(xf, ct), __fmul_rn(yf, st));
    float drho = __fadd_rn(__fmul_rn(-xf, st), __fmul_rn(yf, ct));
    float var_r = __fmul_rn(__fmul_rn(drho, drho), var_t);

    float v = mask[h * WW + w];
    bool valid = (var_t <= 100.0f) && (var_r <= 100.0f) && (v != 0.0f);

    unsigned m = __ballot_sync(0xffffffffu, valid);
    if (m) {
        int lane = threadIdx.x;
        int leader = __ffs(m) - 1;
        int base = 0;
        if (lane == leader) base = atomicAdd(&g_misc[0], __popc(m));
        base = __shfl_sync(0xffffffffu, base, leader);
        if (valid) {
            int idx = base + __popc(m & ((1u << lane) - 1u));
            float sig_t = __fsqrt_rn(__fadd_rn(var_t, 1e-12f));
            float sig_r = __fsqrt_rn(__fadd_rn(var_r, 1e-12f));
            g_pts[idx] = make_float4(theta, rho, sig_t, sig_r);
            g_val[idx] = v;
            atomicAdd(&g_misc[1 + calc_rlo(rho, sig_r)], 1);
        }
    }
}

// ---------------- scan: 360-entry prefix sum (one block) ----------------
__global__ void scan_kernel() {
    __shared__ int tmp[512];
    int t = threadIdx.x;
    tmp[t] = (t < 360) ? g_misc[1 + t] : 0;
    __syncthreads();
    for (int off = 1; off < 512; off <<= 1) {
        int v = (t >= off) ? tmp[t - off] : 0;
        __syncthreads();
        tmp[t] += v;
        __syncthreads();
    }
    if (t < 360) g_boff[t + 1] = tmp[t];
    if (t == 0)  g_boff[0] = 0;
}

// ---------------- cdf: weights, scattered into bucket order ----------------
__global__ void __launch_bounds__(256)
cdf_kernel() {
    __shared__ float tbuf[8][184];
    int lane = threadIdx.x & 31;
    int wl   = threadIdx.x >> 5;
    int warp = blockIdx.x * 8 + wl;
    int n = g_misc[0];

    for (int p = warp; p < n; p += CDF_BLOCKS * 8) {
        float4 pt = g_pts[p];
        float theta = pt.x, rho = pt.y, sig_t = pt.z, sig_r = pt.w;
        float rst = __fdiv_rn(1.0f, sig_t);
        float rsr = __fdiv_rn(1.0f, sig_r);

        // ---- rho window first (gives rlo -> destination bucket slot) ----
        float Wr = fminf(6.5f * sig_r, 62.0f);
        int rklo = max(0,   (int)ceilf ((rho - Wr - RMIN_F) / RBIN_F + 0.5f));
        int rkhi = min(360, (int)floorf((rho + Wr - RMIN_F) / RBIN_F + 0.5f));
        rklo = min(rklo, 360);
        int e = rklo + lane;
        if (e <= rkhi) {
            float ec = __fadd_rn(RMIN_F, __fmul_rn(__fsub_rn((float)e, 0.5f), RBIN_F));
            tbuf[wl][lane] = fcdf((ec - rho) * rsr);
        }
        __syncwarp();
        int lo_b = min(max(0, rklo - 1), 359);   // == calc_rlo(rho, sig_r)
        int hi_b = min(359, rkhi);
        int cnt  = min(max(hi_b - lo_b + 1, 1), 32);
        float v = g_val[p];
        float wr = 0.0f;
        int b = lo_b + lane;
        if (lane < cnt) {
            float c0 = (b     < rklo) ? 0.0f : tbuf[wl][b     - rklo];
            float c1 = (b + 1 > rkhi) ? 1.0f : tbuf[wl][b + 1 - rklo];
            wr = __fmul_rn(__fsub_rn(c1, c0), v);
        }
        int dst = 0;
        if (lane == 0) dst = g_boff[lo_b] + atomicAdd(&g_misc[361 + lo_b], 1);
        dst = __shfl_sync(0xffffffffu, dst, 0);
        g_wr[(size_t)dst * 32 + lane] = wr;
        __syncwarp();

        // ---- theta window -> dense wt[180] at dst ----
        float Wt = 6.5f * sig_t;
        int klo = max(0,   (int)ceilf ((theta - Wt - TMIN_F) / TBIN_F + 0.5f));
        int khi = min(180, (int)floorf((theta + Wt - TMIN_F) / TBIN_F + 0.5f));
        klo = min(klo, 181);
        for (int ee = klo + lane; ee <= khi; ee += 32) {
            float ec = __fadd_rn(TMIN_F, __fmul_rn(__fsub_rn((float)ee, 0.5f), TBIN_F));
            tbuf[wl][ee - klo] = fcdf((ec - theta) * rst);
        }
        __syncwarp();
        float* wtp = g_wt + (size_t)dst * 180;
        for (int j = lane; j < 180; j += 32) {
            float c0 = (j     < klo) ? 0.0f : ((j     > khi) ? 1.0f : tbuf[wl][j     - klo]);
            float c1 = (j + 1 < klo) ? 0.0f : ((j + 1 > khi) ? 1.0f : tbuf[wl][j + 1 - klo]);
            wtp[j] = __fsub_rn(c1, c0);
        }
        __syncwarp();
    }
}

// ---------------- vote: bucketed register accumulation + prefetch ----------------
// blockIdx.x = column group (32 buckets), .y = theta tile (30 rows), .z = split.
// Warp takes a bucket: lane owns column (rlo + lane); 30 rows of acc in regs.
// Software prefetch keeps one iteration of LDG latency in flight; wslot is
// double-buffered so one __syncwarp per iteration suffices.
__global__ void __launch_bounds__(256, 4)
vote_kernel(float* __restrict__ out) {
    __shared__ float  sacc[30 * 64];
    __shared__ float2 wslot[8][2][32];
    int tid = threadIdx.x, lane = tid & 31, warp = tid >> 5;
    int b0 = blockIdx.x * 32;
    int nb = min(32, 360 - b0);
    int tile = blockIdx.y, sp = blockIdx.z;
    int tbase = tile * 30;

    for (int i = tid; i < 30 * 64; i += 256) sacc[i] = 0.0f;
    __syncthreads();

    for (int bi = warp; bi < nb; bi += 8) {
        int b = b0 + bi;
        int s = g_boff[b], e = g_boff[b + 1];
        int p = s + sp;
        if (p >= e) continue;

        float acc[30];
#pragma unroll
        for (int j = 0; j < 30; j++) acc[j] = 0.0f;

        // preload first pair
        int pB = p + NSP;
        bool hB = (pB < e);
        float wrA = g_wr[(size_t)p * 32 + lane];
        float wrB = hB ? g_wr[(size_t)pB * 32 + lane] : 0.0f;
        float wa = 0.0f, wb = 0.0f;
        if (lane < 30) {
            wa = g_wt[(size_t)p * 180 + tbase + lane];
            wb = hB ? g_wt[(size_t)pB * 180 + tbase + lane] : 0.0f;
        }
        int buf = 0;

        while (true) {
            if (lane < 30) wslot[warp][buf][lane] = make_float2(wa, wb);

            // issue next pair's loads before consuming current
            int pn = p + 2 * NSP;
            bool more = (pn < e);
            float wrA1 = 0.0f, wrB1 = 0.0f, wa1 = 0.0f, wb1 = 0.0f;
            if (more) {
                int pnB = pn + NSP;
                bool hB1 = (pnB < e);
                wrA1 = g_wr[(size_t)pn * 32 + lane];
                wrB1 = hB1 ? g_wr[(size_t)pnB * 32 + lane] : 0.0f;
                if (lane < 30) {
                    wa1 = g_wt[(size_t)pn * 180 + tbase + lane];
                    wb1 = hB1 ? g_wt[(size_t)pnB * 180 + tbase + lane] : 0.0f;
                }
            }
            __syncwarp();
#pragma unroll
            for (int j = 0; j < 30; j++) {
                float2 w2 = wslot[warp][buf][j];   // broadcast LDS.64
                acc[j] = fmaf(w2.x, wrA, acc[j]);
                acc[j] = fmaf(w2.y, wrB, acc[j]);
            }
            if (!more) break;
            p = pn; wrA = wrA1; wrB = wrB1; wa = wa1; wb = wb1; buf ^= 1;
        }

        int c = bi + lane;                 // 0..62, in-bounds (<64)
#pragma unroll
        for (int j = 0; j < 30; j++)
            atomicAdd(&sacc[j * 64 + c], acc[j]);
    }

    __syncthreads();
    // float4 global merge: cols b0..b0+63, b0 % 4 == 0 so chunks are aligned
    for (int i = tid; i < (30 * 64) / 4; i += 256) {
        int r = i >> 4, cq = (i & 15) * 4;
        int col = b0 + cq;
        if (col < 360) {
            float4 v = ((const float4*)sacc)[i];
            if (v.x != 0.0f || v.y != 0.0f || v.z != 0.0f || v.w != 0.0f)
                atomicAdd((float4*)(out + (tbase + r) * RBINS + col), v);
        }
    }
}

extern "C" void kernel_launch(void* const* d_in, const int* in_sizes, int n_in,
                              void* d_out, int out_size) {
    const float* img  = (const float*)d_in[0];
    const float* mask = (const float*)d_in[1];
    float* out = (float*)d_out;

    void* misc_ptr = nullptr;
    cudaGetSymbolAddress(&misc_ptr, g_misc);
    cudaMemsetAsync(misc_ptr, 0, sizeof(int) * 721);

    plane_kernel<<<dim3(WW / 32, HH / 8), dim3(32, 8)>>>(img, mask, out);
    scan_kernel<<<1, 512>>>();
    cdf_kernel<<<CDF_BLOCKS, 256>>>();
    vote_kernel<<<dim3(NCG, NTL, NSP), 256>>>(out);
}

// round 15
// speedup vs baseline: 1.1161x; 1.1161x over previous
#include <cuda_runtime.h>
#include <cstdint>

#define HH 512
#define WW 512
#define TBINS 180
#define RBINS 360
#define NPIX (HH*WW)
#define CDF_BLOCKS 2048       // 16384 warps
#define NCG 12                // column groups of 32 buckets
#define NTL 6                 // theta tiles of 30 rows
#define NSP 8                 // pixel splits in vote (R13 value)

// scratch (no cudaMalloc allowed)
static __device__ float4 g_pts[NPIX];       // theta, rho, sig_t, sig_r (raw order)
static __device__ float  g_val[NPIX];       // mask value (raw order)
static __device__ int    g_misc[721];       // [0]=count, [1..360]=bcnt, [361..720]=bfill
static __device__ int    g_boff[361];       // bucket prefix offsets
static __device__ float  g_wt[(size_t)NPIX * 180]; // theta weights, BUCKET order
static __device__ float  g_wr[(size_t)NPIX * 32];  // rho weights (32, zero-pad), BUCKET order

// bin-edge constants
#define TMIN_F (-1.5707963267948966f)
#define TBIN_F ((float)(3.14159265358979323846 / 179.0))
#define RMAX_D 724.07734393502470
#define RMIN_F ((float)(-RMAX_D))
#define RBIN_F ((float)(2.0 * RMAX_D / 359.0))

__device__ __forceinline__ float fcdf(float x) {
    return 0.5f * (1.0f + erff(x * 0.7071067811865476f));
}

// rlo from (rho, sig_r): MUST be identical text in plane and cdf.
__device__ __forceinline__ int calc_rlo(float rho, float sig_r) {
    float Wr = fminf(6.5f * sig_r, 62.0f);
    int rklo = max(0, (int)ceilf((rho - Wr - RMIN_F) / RBIN_F + 0.5f));
    rklo = min(rklo, 360);
    return min(max(0, rklo - 1), 359);
}

// ---------------- plane: fit + validity (bit-exact) + compact + rlo histogram ----------------
__global__ void plane_kernel(const float* __restrict__ img,
                             const float* __restrict__ mask,
                             float* __restrict__ out) {
    int bid = blockIdx.y * (WW / 32) + blockIdx.x;
    int zi = bid * 256 + threadIdx.y * 32 + threadIdx.x;
    if (zi < (TBINS * RBINS) / 4)
        ((float4*)out)[zi] = make_float4(0.f, 0.f, 0.f, 0.f);

    int w = blockIdx.x * 32 + threadIdx.x;
    int h = blockIdx.y * 8  + threadIdx.y;
    int hm = max(h - 1, 0), hp = min(h + 1, HH - 1);
    int wm = max(w - 1, 0), wp = min(w + 1, WW - 1);
    const float* r0 = img + hm * WW;
    const float* r1 = img + h  * WW;
    const float* r2 = img + hp * WW;
    float a00 = r0[wm], a01 = r0[w], a02 = r0[wp];
    float a10 = r1[wm], a11 = r1[w], a12 = r1[wp];
    float a20 = r2[wm], a21 = r2[w], a22 = r2[wp];

    float asum = __fadd_rn(__fadd_rn(__fadd_rn(__fadd_rn(__fadd_rn(
                 -a00, -a01), -a02), a20), a21), a22);
    float bsum = __fadd_rn(__fadd_rn(__fadd_rn(__fadd_rn(__fadd_rn(
                 -a00, a02), -a10), a12), -a20), a22);
    float gsum = __fadd_rn(__fadd_rn(__fadd_rn(__fadd_rn(__fadd_rn(__fadd_rn(
                 __fadd_rn(__fadd_rn(a00, a01), a02), a10), a11), a12), a20), a21), a22);

    float alpha = __fadd_rn(__fdiv_rn(asum, 6.0f), 1e-6f);
    float beta  = __fadd_rn(__fdiv_rn(bsum, 6.0f), 1e-6f);
    float gamma = __fdiv_rn(gsum, 9.0f);

    float rs_arr[3] = { a01, a11, a21 };
    float bd_arr[3] = { -beta, 0.0f, beta };
    float ad_arr[3] = { -alpha, 0.0f, alpha };
    float eps2 = 0.0f;
#pragma unroll
    for (int i = 0; i < 3; i++)
#pragma unroll
        for (int j = 0; j < 3; j++) {
            float r = __fsub_rn(__fsub_rn(__fsub_rn(rs_arr[i], ad_arr[j]), bd_arr[i]), gamma);
            eps2 = __fadd_rn(eps2, __fmul_rn(r, r));
        }
    float nv = __fdiv_rn(eps2, 7.0f);
    float va = __fdiv_rn(nv, 6.0f);

    float aa = __fmul_rn(alpha, alpha);
    float bb = __fmul_rn(beta, beta);
    float g2 = __fadd_rn(aa, bb);
    float num = __fadd_rn(__fmul_rn(bb, va), __fmul_rn(aa, va));
    float var_t = __fdiv_rn(num, __fmul_rn(g2, g2));

    float theta = atanf(__fdiv_rn(beta, alpha));
    float inv = rsqrtf(g2);
    float invs = copysignf(inv, alpha);
    float ct = alpha * invs;
    float st = beta  * invs;
    float xf = (float)h, yf = (float)w;
    float rho  = __fadd_rn(__fmul_rn(xf, ct), __fmul_rn(yf, st));
    float drho = __fadd_rn(__fmul_rn(-xf, st), __fmul_rn(yf, ct));
    float var_r = __fmul_rn(__fmul_rn(drho, drho), var_t);

    float v = mask[h * WW + w];
    bool valid = (var_t <= 100.0f) && (var_r <= 100.0f) && (v != 0.0f);

    unsigned m = __ballot_sync(0xffffffffu, valid);
    if (m) {
        int lane = threadIdx.x;
        int leader = __ffs(m) - 1;
        int base = 0;
        if (lane == leader) base = atomicAdd(&g_misc[0], __popc(m));
        base = __shfl_sync(0xffffffffu, base, leader);
        if (valid) {
            int idx = base + __popc(m & ((1u << lane) - 1u));
            float sig_t = __fsqrt_rn(__fadd_rn(var_t, 1e-12f));
            float sig_r = __fsqrt_rn(__fadd_rn(var_r, 1e-12f));
            g_pts[idx] = make_float4(theta, rho, sig_t, sig_r);
            g_val[idx] = v;
            atomicAdd(&g_misc[1 + calc_rlo(rho, sig_r)], 1);
        }
    }
}

// ---------------- scan: 360-entry prefix sum (one block) ----------------
__global__ void scan_kernel() {
    __shared__ int tmp[512];
    int t = threadIdx.x;
    tmp[t] = (t < 360) ? g_misc[1 + t] : 0;
    __syncthreads();
    for (int off = 1; off < 512; off <<= 1) {
        int v = (t >= off) ? tmp[t - off] : 0;
        __syncthreads();
        tmp[t] += v;
        __syncthreads();
    }
    if (t < 360) g_boff[t + 1] = tmp[t];
    if (t == 0)  g_boff[0] = 0;
}

// ---------------- cdf: weights, scattered into bucket order ----------------
__global__ void __launch_bounds__(256)
cdf_kernel() {
    __shared__ float tbuf[8][184];
    int lane = threadIdx.x & 31;
    int wl   = threadIdx.x >> 5;
    int warp = blockIdx.x * 8 + wl;
    int n = g_misc[0];

    for (int p = warp; p < n; p += CDF_BLOCKS * 8) {
        float4 pt = g_pts[p];
        float theta = pt.x, rho = pt.y, sig_t = pt.z, sig_r = pt.w;
        float rst = __fdiv_rn(1.0f, sig_t);
        float rsr = __fdiv_rn(1.0f, sig_r);

        // ---- rho window first (gives rlo -> destination bucket slot) ----
        float Wr = fminf(6.5f * sig_r, 62.0f);
        int rklo = max(0,   (int)ceilf ((rho - Wr - RMIN_F) / RBIN_F + 0.5f));
        int rkhi = min(360, (int)floorf((rho + Wr - RMIN_F) / RBIN_F + 0.5f));
        rklo = min(rklo, 360);
        int e = rklo + lane;
        if (e <= rkhi) {
            float ec = __fadd_rn(RMIN_F, __fmul_rn(__fsub_rn((float)e, 0.5f), RBIN_F));
            tbuf[wl][lane] = fcdf((ec - rho) * rsr);
        }
        __syncwarp();
        int lo_b = min(max(0, rklo - 1), 359);   // == calc_rlo(rho, sig_r)
        int hi_b = min(359, rkhi);
        int cnt  = min(max(hi_b - lo_b + 1, 1), 32);
        float v = g_val[p];
        float wr = 0.0f;
        int b = lo_b + lane;
        if (lane < cnt) {
            float c0 = (b     < rklo) ? 0.0f : tbuf[wl][b     - rklo];
            float c1 = (b + 1 > rkhi) ? 1.0f : tbuf[wl][b + 1 - rklo];
            wr = __fmul_rn(__fsub_rn(c1, c0), v);
        }
        int dst = 0;
        if (lane == 0) dst = g_boff[lo_b] + atomicAdd(&g_misc[361 + lo_b], 1);
        dst = __shfl_sync(0xffffffffu, dst, 0);
        g_wr[(size_t)dst * 32 + lane] = wr;
        __syncwarp();

        // ---- theta window -> dense wt[180] at dst ----
        float Wt = 6.5f * sig_t;
        int klo = max(0,   (int)ceilf ((theta - Wt - TMIN_F) / TBIN_F + 0.5f));
        int khi = min(180, (int)floorf((theta + Wt - TMIN_F) / TBIN_F + 0.5f));
        klo = min(klo, 181);
        for (int ee = klo + lane; ee <= khi; ee += 32) {
            float ec = __fadd_rn(TMIN_F, __fmul_rn(__fsub_rn((float)ee, 0.5f), TBIN_F));
            tbuf[wl][ee - klo] = fcdf((ec - theta) * rst);
        }
        __syncwarp();
        float* wtp = g_wt + (size_t)dst * 180;
        for (int j = lane; j < 180; j += 32) {
            float c0 = (j     < klo) ? 0.0f : ((j     > khi) ? 1.0f : tbuf[wl][j     - klo]);
            float c1 = (j + 1 < klo) ? 0.0f : ((j + 1 > khi) ? 1.0f : tbuf[wl][j + 1 - klo]);
            wtp[j] = __fsub_rn(c1, c0);
        }
        __syncwarp();
    }
}

// ---------------- vote: bucketed register accumulation + prefetch (NSP=8) ----------------
// blockIdx.x = column group (32 buckets), .y = theta tile (30 rows), .z = split.
// Warp takes a bucket: lane owns column (rlo + lane); 30 rows of acc in regs.
// Software prefetch keeps one pair of LDG latency in flight; wslot is
// double-buffered so one __syncwarp per iteration suffices.
__global__ void __launch_bounds__(256, 4)
vote_kernel(float* __restrict__ out) {
    __shared__ float  sacc[30 * 64];
    __shared__ float2 wslot[8][2][32];
    int tid = threadIdx.x, lane = tid & 31, warp = tid >> 5;
    int b0 = blockIdx.x * 32;
    int nb = min(32, 360 - b0);
    int tile = blockIdx.y, sp = blockIdx.z;
    int tbase = tile * 30;

    for (int i = tid; i < 30 * 64; i += 256) sacc[i] = 0.0f;
    __syncthreads();

    for (int bi = warp; bi < nb; bi += 8) {
        int b = b0 + bi;
        int s = g_boff[b], e = g_boff[b + 1];
        int p = s + sp;
        if (p >= e) continue;

        float acc[30];
#pragma unroll
        for (int j = 0; j < 30; j++) acc[j] = 0.0f;

        // preload first pair
        int pB = p + NSP;
        bool hB = (pB < e);
        float wrA = g_wr[(size_t)p * 32 + lane];
        float wrB = hB ? g_wr[(size_t)pB * 32 + lane] : 0.0f;
        float wa = 0.0f, wb = 0.0f;
        if (lane < 30) {
            wa = g_wt[(size_t)p * 180 + tbase + lane];
            wb = hB ? g_wt[(size_t)pB * 180 + tbase + lane] : 0.0f;
        }
        int buf = 0;

        while (true) {
            if (lane < 30) wslot[warp][buf][lane] = make_float2(wa, wb);

            // issue next pair's loads before consuming current
            int pn = p + 2 * NSP;
            bool more = (pn < e);
            float wrA1 = 0.0f, wrB1 = 0.0f, wa1 = 0.0f, wb1 = 0.0f;
            if (more) {
                int pnB = pn + NSP;
                bool hB1 = (pnB < e);
                wrA1 = g_wr[(size_t)pn * 32 + lane];
                wrB1 = hB1 ? g_wr[(size_t)pnB * 32 + lane] : 0.0f;
                if (lane < 30) {
                    wa1 = g_wt[(size_t)pn * 180 + tbase + lane];
                    wb1 = hB1 ? g_wt[(size_t)pnB * 180 + tbase + lane] : 0.0f;
                }
            }
            __syncwarp();
#pragma unroll
            for (int j = 0; j < 30; j++) {
                float2 w2 = wslot[warp][buf][j];   // broadcast LDS.64
                acc[j] = fmaf(w2.x, wrA, acc[j]);
                acc[j] = fmaf(w2.y, wrB, acc[j]);
            }
            if (!more) break;
            p = pn; wrA = wrA1; wrB = wrB1; wa = wa1; wb = wb1; buf ^= 1;
        }

        int c = bi + lane;                 // 0..62, in-bounds (<64)
#pragma unroll
        for (int j = 0; j < 30; j++)
            atomicAdd(&sacc[j * 64 + c], acc[j]);
    }

    __syncthreads();
    // float4 global merge: cols b0..b0+63, b0 % 4 == 0 so chunks are aligned
    for (int i = tid; i < (30 * 64) / 4; i += 256) {
        int r = i >> 4, cq = (i & 15) * 4;
        int col = b0 + cq;
        if (col < 360) {
            float4 v = ((const float4*)sacc)[i];
            if (v.x != 0.0f || v.y != 0.0f || v.z != 0.0f || v.w != 0.0f)
                atomicAdd((float4*)(out + (tbase + r) * RBINS + col), v);
        }
    }
}

extern "C" void kernel_launch(void* const* d_in, const int* in_sizes, int n_in,
                              void* d_out, int out_size) {
    const float* img  = (const float*)d_in[0];
    const float* mask = (const float*)d_in[1];
    float* out = (float*)d_out;

    void* misc_ptr = nullptr;
    cudaGetSymbolAddress(&misc_ptr, g_misc);
    cudaMemsetAsync(misc_ptr, 0, sizeof(int) * 721);

    plane_kernel<<<dim3(WW / 32, HH / 8), dim3(32, 8)>>>(img, mask, out);
    scan_kernel<<<1, 512>>>();
    cdf_kernel<<<CDF_BLOCKS, 256>>>();
    vote_kernel<<<dim3(NCG, NTL, NSP), 256>>>(out);
}

// round 16
// speedup vs baseline: 1.1745x; 1.0523x over previous
#include <cuda_runtime.h>
#include <cstdint>

#define HH 512
#define WW 512
#define TBINS 180
#define RBINS 360
#define NPIX (HH*WW)
#define CDF_BLOCKS 2048       // 16384 warps
#define NCG 12                // column groups of 32 buckets
#define NTL 6                 // theta tiles of 30 rows
#define NSLOT 96              // x-slots distributed over groups by population

// scratch (no cudaMalloc allowed)
static __device__ float4 g_pts[NPIX];       // theta, rho, sig_t, sig_r (raw order)
static __device__ float  g_val[NPIX];       // mask value (raw order)
static __device__ int    g_misc[721];       // [0]=count, [1..360]=bcnt, [361..720]=bfill
static __device__ int    g_boff[361];       // bucket prefix offsets
static __device__ int    g_sched[NCG + 1];  // slot prefix per column group
static __device__ float  g_wt[(size_t)NPIX * 180]; // theta weights, BUCKET order
static __device__ float  g_wr[(size_t)NPIX * 32];  // rho weights (32, zero-pad), BUCKET order

// bin-edge constants
#define TMIN_F (-1.5707963267948966f)
#define TBIN_F ((float)(3.14159265358979323846 / 179.0))
#define RMAX_D 724.07734393502470
#define RMIN_F ((float)(-RMAX_D))
#define RBIN_F ((float)(2.0 * RMAX_D / 359.0))

__device__ __forceinline__ float fcdf(float x) {
    return 0.5f * (1.0f + erff(x * 0.7071067811865476f));
}

// rlo from (rho, sig_r): MUST be identical text in plane and cdf.
__device__ __forceinline__ int calc_rlo(float rho, float sig_r) {
    float Wr = fminf(6.5f * sig_r, 62.0f);
    int rklo = max(0, (int)ceilf((rho - Wr - RMIN_F) / RBIN_F + 0.5f));
    rklo = min(rklo, 360);
    return min(max(0, rklo - 1), 359);
}

// ---------------- plane: fit + validity (bit-exact) + compact + rlo histogram ----------------
__global__ void plane_kernel(const float* __restrict__ img,
                             const float* __restrict__ mask,
                             float* __restrict__ out) {
    int bid = blockIdx.y * (WW / 32) + blockIdx.x;
    int zi = bid * 256 + threadIdx.y * 32 + threadIdx.x;
    if (zi < (TBINS * RBINS) / 4)
        ((float4*)out)[zi] = make_float4(0.f, 0.f, 0.f, 0.f);

    int w = blockIdx.x * 32 + threadIdx.x;
    int h = blockIdx.y * 8  + threadIdx.y;
    int hm = max(h - 1, 0), hp = min(h + 1, HH - 1);
    int wm = max(w - 1, 0), wp = min(w + 1, WW - 1);
    const float* r0 = img + hm * WW;
    const float* r1 = img + h  * WW;
    const float* r2 = img + hp * WW;
    float a00 = r0[wm], a01 = r0[w], a02 = r0[wp];
    float a10 = r1[wm], a11 = r1[w], a12 = r1[wp];
    float a20 = r2[wm], a21 = r2[w], a22 = r2[wp];

    float asum = __fadd_rn(__fadd_rn(__fadd_rn(__fadd_rn(__fadd_rn(
                 -a00, -a01), -a02), a20), a21), a22);
    float bsum = __fadd_rn(__fadd_rn(__fadd_rn(__fadd_rn(__fadd_rn(
                 -a00, a02), -a10), a12), -a20), a22);
    float gsum = __fadd_rn(__fadd_rn(__fadd_rn(__fadd_rn(__fadd_rn(__fadd_rn(
                 __fadd_rn(__fadd_rn(a00, a01), a02), a10), a11), a12), a20), a21), a22);

    float alpha = __fadd_rn(__fdiv_rn(asum, 6.0f), 1e-6f);
    float beta  = __fadd_rn(__fdiv_rn(bsum, 6.0f), 1e-6f);
    float gamma = __fdiv_rn(gsum, 9.0f);

    float rs_arr[3] = { a01, a11, a21 };
    float bd_arr[3] = { -beta, 0.0f, beta };
    float ad_arr[3] = { -alpha, 0.0f, alpha };
    float eps2 = 0.0f;
#pragma unroll
    for (int i = 0; i < 3; i++)
#pragma unroll
        for (int j = 0; j < 3; j++) {
            float r = __fsub_rn(__fsub_rn(__fsub_rn(rs_arr[i], ad_arr[j]), bd_arr[i]), gamma);
            eps2 = __fadd_rn(eps2, __fmul_rn(r, r));
        }
    float nv = __fdiv_rn(eps2, 7.0f);
    float va = __fdiv_rn(nv, 6.0f);

    float aa = __fmul_rn(alpha, alpha);
    float bb = __fmul_rn(beta, beta);
    float g2 = __fadd_rn(aa, bb);
    float num = __fadd_rn(__fmul_rn(bb, va), __fmul_rn(aa, va));
    float var_t = __fdiv_rn(num, __fmul_rn(g2, g2));

    float theta = atanf(__fdiv_rn(beta, alpha));
    float inv = rsqrtf(g2);
    float invs = copysignf(inv, alpha);
    float ct = alpha * invs;
    float st = beta  * invs;
    float xf = (float)h, yf = (float)w;
    float rho  = __fadd_rn(__fmul_rn(xf, ct), __fmul_rn(yf, st));
    float drho = __fadd_rn(__fmul_rn(-xf, st), __fmul_rn(yf, ct));
    float var_r = __fmul_rn(__fmul_rn(drho, drho), var_t);

    float v = mask[h * WW + w];
    bool valid = (var_t <= 100.0f) && (var_r <= 100.0f) && (v != 0.0f);

    unsigned m = __ballot_sync(0xffffffffu, valid);
    if (m) {
        int lane = threadIdx.x;
        int leader = __ffs(m) - 1;
        int base = 0;
        if (lane == leader) base = atomicAdd(&g_misc[0], __popc(m));
        base = __shfl_sync(0xffffffffu, base, leader);
        if (valid) {
            int idx = base + __popc(m & ((1u << lane) - 1u));
            float sig_t = __fsqrt_rn(__fadd_rn(var_t, 1e-12f));
            float sig_r = __fsqrt_rn(__fadd_rn(var_r, 1e-12f));
            g_pts[idx] = make_float4(theta, rho, sig_t, sig_r);
            g_val[idx] = v;
            atomicAdd(&g_misc[1 + calc_rlo(rho, sig_r)], 1);
        }
    }
}

// ---------------- scan: prefix sum + proportional slot schedule ----------------
__global__ void scan_kernel() {
    __shared__ int tmp[512];
    int t = threadIdx.x;
    tmp[t] = (t < 360) ? g_misc[1 + t] : 0;
    __syncthreads();
    for (int off = 1; off < 512; off <<= 1) {
        int v = (t >= off) ? tmp[t - off] : 0;
        __syncthreads();
        tmp[t] += v;
        __syncthreads();
    }
    if (t < 360) g_boff[t + 1] = tmp[t];
    if (t == 0)  g_boff[0] = 0;
    __syncthreads();
    if (t == 0) {
        int total = tmp[359];
        int acc = 0;
        for (int g = 0; g < NCG; g++) {
            int hi = min(32 * (g + 1), 360);
            int lo = 32 * g;
            int Pg = tmp[hi - 1] - (lo ? tmp[lo - 1] : 0);
            int sl = (total > 0) ? (1 + (84 * Pg) / total) : 1;
            g_sched[g] = acc;
            acc += sl;
        }
        g_sched[NCG] = acc;   // <= 96
    }
}

// ---------------- cdf: weights, scattered into bucket order ----------------
__global__ void __launch_bounds__(256)
cdf_kernel() {
    __shared__ float tbuf[8][184];
    int lane = threadIdx.x & 31;
    int wl   = threadIdx.x >> 5;
    int warp = blockIdx.x * 8 + wl;
    int n = g_misc[0];

    for (int p = warp; p < n; p += CDF_BLOCKS * 8) {
        float4 pt = g_pts[p];
        float theta = pt.x, rho = pt.y, sig_t = pt.z, sig_r = pt.w;
        float rst = __fdiv_rn(1.0f, sig_t);
        float rsr = __fdiv_rn(1.0f, sig_r);

        // ---- rho window first (gives rlo -> destination bucket slot) ----
        float Wr = fminf(6.5f * sig_r, 62.0f);
        int rklo = max(0,   (int)ceilf ((rho - Wr - RMIN_F) / RBIN_F + 0.5f));
        int rkhi = min(360, (int)floorf((rho + Wr - RMIN_F) / RBIN_F + 0.5f));
        rklo = min(rklo, 360);
        int e = rklo + lane;
        if (e <= rkhi) {
            float ec = __fadd_rn(RMIN_F, __fmul_rn(__fsub_rn((float)e, 0.5f), RBIN_F));
            tbuf[wl][lane] = fcdf((ec - rho) * rsr);
        }
        __syncwarp();
        int lo_b = min(max(0, rklo - 1), 359);   // == calc_rlo(rho, sig_r)
        int hi_b = min(359, rkhi);
        int cnt  = min(max(hi_b - lo_b + 1, 1), 32);
        float v = g_val[p];
        float wr = 0.0f;
        int b = lo_b + lane;
        if (lane < cnt) {
            float c0 = (b     < rklo) ? 0.0f : tbuf[wl][b     - rklo];
            float c1 = (b + 1 > rkhi) ? 1.0f : tbuf[wl][b + 1 - rklo];
            wr = __fmul_rn(__fsub_rn(c1, c0), v);
        }
        int dst = 0;
        if (lane == 0) dst = g_boff[lo_b] + atomicAdd(&g_misc[361 + lo_b], 1);
        dst = __shfl_sync(0xffffffffu, dst, 0);
        g_wr[(size_t)dst * 32 + lane] = wr;
        __syncwarp();

        // ---- theta window -> dense wt[180] at dst ----
        float Wt = 6.5f * sig_t;
        int klo = max(0,   (int)ceilf ((theta - Wt - TMIN_F) / TBIN_F + 0.5f));
        int khi = min(180, (int)floorf((theta + Wt - TMIN_F) / TBIN_F + 0.5f));
        klo = min(klo, 181);
        for (int ee = klo + lane; ee <= khi; ee += 32) {
            float ec = __fadd_rn(TMIN_F, __fmul_rn(__fsub_rn((float)ee, 0.5f), TBIN_F));
            tbuf[wl][ee - klo] = fcdf((ec - theta) * rst);
        }
        __syncwarp();
        float* wtp = g_wt + (size_t)dst * 180;
        for (int j = lane; j < 180; j += 32) {
            float c0 = (j     < klo) ? 0.0f : ((j     > khi) ? 1.0f : tbuf[wl][j     - klo]);
            float c1 = (j + 1 < klo) ? 0.0f : ((j + 1 > khi) ? 1.0f : tbuf[wl][j + 1 - klo]);
            wtp[j] = __fsub_rn(c1, c0);
        }
        __syncwarp();
    }
}

// ---------------- vote: bucketed register accumulation, balanced ----------------
// blockIdx.x = slot (maps to (group, split) via g_sched, splits proportional
// to group population), blockIdx.y = theta tile. Warps steal buckets from a
// smem ticket. Lane owns column (rlo + lane); 30 rows of acc in registers.
__global__ void __launch_bounds__(256, 4)
vote_kernel(float* __restrict__ out) {
    __shared__ float  sacc[30 * 64];
    __shared__ float2 wslot[8][2][32];
    __shared__ int    sbkt;
    int s = blockIdx.x;
    if (s >= g_sched[NCG]) return;     // uniform early-out (unused slots)

    int g = 0;
    for (int k = 1; k < NCG; k++) if (g_sched[k] <= s) g = k;
    int sp  = s - g_sched[g];
    int nsp = g_sched[g + 1] - g_sched[g];

    int tid = threadIdx.x, lane = tid & 31, warp = tid >> 5;
    int b0 = g * 32;
    int nb = min(32, 360 - b0);
    int tbase = blockIdx.y * 30;

    for (int i = tid; i < 30 * 64; i += 256) sacc[i] = 0.0f;
    if (tid == 0) sbkt = 0;
    __syncthreads();

    while (true) {
        int k;
        if (lane == 0) k = atomicAdd(&sbkt, 1);
        k = __shfl_sync(0xffffffffu, k, 0);
        if (k >= nb) break;
        int b = b0 + k;
        int bs = g_boff[b], be = g_boff[b + 1];
        int p = bs + sp;
        if (p >= be) continue;

        float acc[30];
#pragma unroll
        for (int j = 0; j < 30; j++) acc[j] = 0.0f;

        // preload first pair
        int pB = p + nsp;
        bool hB = (pB < be);
        float wrA = g_wr[(size_t)p * 32 + lane];
        float wrB = hB ? g_wr[(size_t)pB * 32 + lane] : 0.0f;
        float wa = 0.0f, wb = 0.0f;
        if (lane < 30) {
            wa = g_wt[(size_t)p * 180 + tbase + lane];
            wb = hB ? g_wt[(size_t)pB * 180 + tbase + lane] : 0.0f;
        }
        int buf = 0;

        while (true) {
            if (lane < 30) wslot[warp][buf][lane] = make_float2(wa, wb);

            int pn = p + 2 * nsp;
            bool more = (pn < be);
            float wrA1 = 0.0f, wrB1 = 0.0f, wa1 = 0.0f, wb1 = 0.0f;
            if (more) {
                int pnB = pn + nsp;
                bool hB1 = (pnB < be);
                wrA1 = g_wr[(size_t)pn * 32 + lane];
                wrB1 = hB1 ? g_wr[(size_t)pnB * 32 + lane] : 0.0f;
                if (lane < 30) {
                    wa1 = g_wt[(size_t)pn * 180 + tbase + lane];
                    wb1 = hB1 ? g_wt[(size_t)pnB * 180 + tbase + lane] : 0.0f;
                }
            }
            __syncwarp();
#pragma unroll
            for (int j = 0; j < 30; j++) {
                float2 w2 = wslot[warp][buf][j];   // broadcast LDS.64
                acc[j] = fmaf(w2.x, wrA, acc[j]);
                acc[j] = fmaf(w2.y, wrB, acc[j]);
            }
            if (!more) break;
            p = pn; wrA = wrA1; wrB = wrB1; wa = wa1; wb = wb1; buf ^= 1;
        }

        int c = k + lane;                  // 0..62, in-bounds (<64)
#pragma unroll
        for (int j = 0; j < 30; j++)
            atomicAdd(&sacc[j * 64 + c], acc[j]);
    }

    __syncthreads();
    // float4 global merge: cols b0..b0+63, b0 % 4 == 0 so chunks are aligned
    for (int i = tid; i < (30 * 64) / 4; i += 256) {
        int r = i >> 4, cq = (i & 15) * 4;
        int col = b0 + cq;
        if (col < 360) {
            float4 v = ((const float4*)sacc)[i];
            if (v.x != 0.0f || v.y != 0.0f || v.z != 0.0f || v.w != 0.0f)
                atomicAdd((float4*)(out + (tbase + r) * RBINS + col), v);
        }
    }
}

extern "C" void kernel_launch(void* const* d_in, const int* in_sizes, int n_in,
                              void* d_out, int out_size) {
    const float* img  = (const float*)d_in[0];
    const float* mask = (const float*)d_in[1];
    float* out = (float*)d_out;

    void* misc_ptr = nullptr;
    cudaGetSymbolAddress(&misc_ptr, g_misc);
    cudaMemsetAsync(misc_ptr, 0, sizeof(int) * 721);

    plane_kernel<<<dim3(WW / 32, HH / 8), dim3(32, 8)>>>(img, mask, out);
    scan_kernel<<<1, 512>>>();
    cdf_kernel<<<CDF_BLOCKS, 256>>>();
    vote_kernel<<<dim3(NSLOT, NTL), 256>>>(out);
}